// round 1
// baseline (speedup 1.0000x reference)
#include <cuda_runtime.h>
#include <math.h>
#include <float.h>

#define NBATCH 8
#define SL 4096
#define D 128
#define NH 8
#define NB 64        // buckets per hash
#define BS 64        // bucket/chunk size
#define NC 512       // total chunks per batch (NH * NB)
#define NSL (NH*SL)  // 32768 sorted slots per batch
#define KSTR 129     // padded smem row stride (floats) for K/V
#define SCALE 0.08838834764831845f  // 128^-0.5

// ---------------- scratch (static device globals; no runtime alloc) ----------------
__device__ unsigned char g_bkt[NBATCH][NH][SL];          // local bucket id per (b,h,s)
__device__ int           g_st[NBATCH][NSL];              // sorted slot -> token position
__device__ int           g_slotof[NBATCH][NH][SL];       // (h,s) -> sorted slot (undo_sort)
__device__ unsigned      g_locs[NBATCH][SL*NH];          // per token: bucket*512 + chunk, per hash
__device__ float         g_slse[NBATCH][NSL];            // per-slot logsumexp
__device__ float         g_so[(size_t)NBATCH*NSL*D];     // per-slot attention output (128 MB)

// ---------------- K1: LSH bucket assignment ----------------
// grid (128, NH, NBATCH), block 256. Each block: 32 tokens for one (b,h).
__global__ __launch_bounds__(256) void k1_buckets(const float* __restrict__ qk,
                                                  const float* __restrict__ rot) {
    __shared__ float rotS[D*32];    // rotations[:, h, :]  (d-major, 32 per d) 16KB
    __shared__ float qrows[32*D];   // 32 token rows        16KB
    int stile = blockIdx.x, h = blockIdx.y, b = blockIdx.z;
    int tid = threadIdx.x, w = tid >> 5, l = tid & 31;

    for (int i = tid; i < D*32; i += 256) {
        int d = i >> 5, n = i & 31;
        rotS[i] = rot[d*(NH*32) + h*32 + n];
    }
    const float* qb = qk + ((size_t)b*SL + (size_t)stile*32)*D;
    for (int r = w; r < 32; r += 8)
        ((float4*)(qrows + r*D))[l] = ((const float4*)(qb + r*D))[l];
    __syncthreads();

    #pragma unroll
    for (int k = 0; k < 4; k++) {
        int r = w*4 + k;
        const float* qr = qrows + r*D;
        float acc = 0.f;
        #pragma unroll 8
        for (int d = 0; d < D; d++) acc += qr[d] * rotS[d*32 + l];
        // candidates: (+acc, l) and (-acc, l+32); argmax with lowest-index tie-break
        float bv = acc; int bi = l;
        float nv = -acc;
        if (nv > bv) { bv = nv; bi = l + 32; }
        #pragma unroll
        for (int off = 16; off > 0; off >>= 1) {
            float ov = __shfl_xor_sync(0xffffffffu, bv, off);
            int   oi = __shfl_xor_sync(0xffffffffu, bi, off);
            if (ov > bv || (ov == bv && oi < bi)) { bv = ov; bi = oi; }
        }
        if (l == 0) g_bkt[b][h][stile*32 + r] = (unsigned char)bi;
    }
}

// ---------------- K2: stable counting sort per (b,h) ----------------
// grid (NH, NBATCH), block 256. Exact replica of argsort by (bucket, position).
__global__ __launch_bounds__(256) void k2_sort() {
    __shared__ unsigned char  bkt[SL];          // 4KB
    __shared__ unsigned short cnt[NB*257];      // per-thread per-bucket hist, padded
    __shared__ int tot[NB];
    __shared__ int base[NB];
    int h = blockIdx.x, b = blockIdx.y;
    int t = threadIdx.x;

    ((int4*)bkt)[t] = ((const int4*)&g_bkt[b][h][0])[t];   // 16 bytes/thread
    for (int i = t; i < NB*257; i += 256) cnt[i] = 0;
    __syncthreads();

    #pragma unroll
    for (int j = 0; j < 16; j++) {
        int c = bkt[t*16 + j];
        cnt[c*257 + t]++;
    }
    __syncthreads();

    if (t < NB) {
        int run = 0;
        for (int i = 0; i < 256; i++) {
            int v = cnt[t*257 + i];
            cnt[t*257 + i] = (unsigned short)run;
            run += v;
        }
        tot[t] = run;
    }
    __syncthreads();
    if (t == 0) {
        int run = 0;
        for (int c = 0; c < NB; c++) { base[c] = run; run += tot[c]; }
    }
    __syncthreads();

    #pragma unroll
    for (int j = 0; j < 16; j++) {
        int i = t*16 + j;                         // i == token position s (stable in s)
        int c = bkt[i];
        int r = cnt[c*257 + t]++;
        int slot = h*SL + base[c] + r;            // global sorted slot
        g_st[b][slot] = i;
        g_slotof[b][h][i] = slot;
        g_locs[b][i*NH + h] = (unsigned)(((h*NB + c) << 9) | (slot >> 6));
    }
}

// ---------------- K3: chunked attention ----------------
// grid (NC, NBATCH), block 512, ~203KB dynamic smem, 1 CTA/SM.
__global__ __launch_bounds__(512) void k3_attn(const float* __restrict__ qk,
                                               const float* __restrict__ vglob) {
    extern __shared__ float sm[];
    float*    Ksh   = sm;                         // [128][129] normalized keys
    float*    Vsh   = Ksh + 128*KSTR;             // [128][129]
    float*    Qsh   = Vsh + 128*KSTR;             // [64][128]
    float*    Psh   = Qsh + 64*D;                 // [64][128]
    int*      stk   = (int*)(Psh + 64*D);         // [128] key tokens (0..63 == query tokens)
    unsigned* locsk = (unsigned*)(stk + 128);     // [128][9] (padded -> conflict-free)

    int c = blockIdx.x, b = blockIdx.y;
    int cprev = (c + NC - 1) % NC;
    int tid = threadIdx.x, w = tid >> 5, l = tid & 31;

    if (tid < 128)
        stk[tid] = g_st[b][(tid < 64 ? c : cprev)*BS + (tid & 63)];
    __syncthreads();

    // per-token locs table (8 u32 per token)
    for (int i = tid; i < 128*NH; i += 512) {
        int z = i >> 3, hh = i & 7;
        locsk[z*9 + hh] = g_locs[b][stk[z]*NH + hh];
    }

    // gather rows: warp w handles rows w, w+16, ...
    const float* qkb = qk    + (size_t)b*SL*D;
    const float* vb  = vglob + (size_t)b*SL*D;
    for (int r = w; r < 128; r += 16) {
        int tok = stk[r];
        float4 kv = ((const float4*)(qkb + (size_t)tok*D))[l];
        float ss = kv.x*kv.x + kv.y*kv.y + kv.z*kv.z + kv.w*kv.w;
        #pragma unroll
        for (int off = 16; off > 0; off >>= 1) ss += __shfl_xor_sync(0xffffffffu, ss, off);
        float rn = 1.f / fmaxf(sqrtf(ss), 1e-12f);
        float* kd = Ksh + r*KSTR + 4*l;
        kd[0] = kv.x*rn; kd[1] = kv.y*rn; kd[2] = kv.z*rn; kd[3] = kv.w*rn;
        float4 vv = ((const float4*)(vb + (size_t)tok*D))[l];
        float* vd = Vsh + r*KSTR + 4*l;
        vd[0] = vv.x; vd[1] = vv.y; vd[2] = vv.z; vd[3] = vv.w;
        if (r < 64) ((float4*)(Qsh + r*D))[l] = kv;   // queries unnormalized
    }
    __syncthreads();

    // ---- dots: thread owns q = 4w..4w+3, z = l+32j (j<4) ----
    float acc[4][4];
    #pragma unroll
    for (int qi = 0; qi < 4; qi++)
        #pragma unroll
        for (int j = 0; j < 4; j++) acc[qi][j] = 0.f;

    for (int d = 0; d < D; d += 4) {
        float kk[4][4];
        #pragma unroll
        for (int j = 0; j < 4; j++) {
            const float* kp = Ksh + (l + 32*j)*KSTR + d;
            kk[j][0] = kp[0]; kk[j][1] = kp[1]; kk[j][2] = kp[2]; kk[j][3] = kp[3];
        }
        #pragma unroll
        for (int qi = 0; qi < 4; qi++) {
            float4 qv = *(const float4*)(Qsh + (w*4 + qi)*D + d);
            #pragma unroll
            for (int j = 0; j < 4; j++)
                acc[qi][j] += qv.x*kk[j][0] + qv.y*kk[j][1] + qv.z*kk[j][2] + qv.w*kk[j][3];
        }
    }

    // ---- masks + duplicate-count correction ----
    int hq = c >> 6, hkp = cprev >> 6;
    int tk[4], bk[4], zz[4];
    #pragma unroll
    for (int j = 0; j < 4; j++) {
        int z = l + 32*j; zz[j] = z;
        tk[j] = stk[z];
        int hk = (z < 64) ? hq : hkp;
        bk[j] = (int)(locsk[z*9 + hk] >> 9);
    }
    #pragma unroll
    for (int qi = 0; qi < 4; qi++) {
        int q  = w*4 + qi;
        int tq = stk[q];
        int bq = (int)(locsk[q*9 + hq] >> 9);
        #pragma unroll
        for (int j = 0; j < 4; j++) {
            float val = acc[qi][j] * SCALE;
            if (tq <  tk[j]) val = -FLT_MAX;     // causal
            if (tq == tk[j]) val = -10000.0f;    // self
            if (bq != bk[j]) val = -FLT_MAX;     // cross-bucket
            acc[qi][j] = val;
        }
        int cntj[4] = {0,0,0,0};
        #pragma unroll
        for (int hh = 0; hh < NH; hh++) {
            unsigned lq = locsk[q*9 + hh];
            #pragma unroll
            for (int j = 0; j < 4; j++) {
                unsigned lk  = locsk[zz[j]*9 + hh];
                unsigned lk2 = (lk & ~511u) | ((lk + 1u) & 511u);
                cntj[j] += (lq == lk) + (lq == lk2);
            }
        }
        #pragma unroll
        for (int j = 0; j < 4; j++)
            acc[qi][j] -= logf((float)cntj[j] + 1e-9f);
    }

    // ---- softmax per q-row (row fully within this warp) ----
    #pragma unroll
    for (int qi = 0; qi < 4; qi++) {
        float m = fmaxf(fmaxf(acc[qi][0], acc[qi][1]), fmaxf(acc[qi][2], acc[qi][3]));
        #pragma unroll
        for (int off = 16; off > 0; off >>= 1) m = fmaxf(m, __shfl_xor_sync(0xffffffffu, m, off));
        float s_ = 0.f;
        #pragma unroll
        for (int j = 0; j < 4; j++) s_ += expf(acc[qi][j] - m);
        #pragma unroll
        for (int off = 16; off > 0; off >>= 1) s_ += __shfl_xor_sync(0xffffffffu, s_, off);
        float lse = m + logf(s_);
        if (l == 0) g_slse[b][c*BS + w*4 + qi] = lse;
        #pragma unroll
        for (int j = 0; j < 4; j++)
            Psh[(w*4 + qi)*D + zz[j]] = expf(acc[qi][j] - lse);
    }
    __syncthreads();

    // ---- PV: thread owns q = 4w..4w+3, dcol = l+32j ----
    float o[4][4];
    #pragma unroll
    for (int qi = 0; qi < 4; qi++)
        #pragma unroll
        for (int j = 0; j < 4; j++) o[qi][j] = 0.f;

    for (int z4 = 0; z4 < 128; z4 += 4) {
        float p4[4][4];
        #pragma unroll
        for (int qi = 0; qi < 4; qi++) {
            float4 pv = *(const float4*)(Psh + (w*4 + qi)*D + z4);
            p4[qi][0] = pv.x; p4[qi][1] = pv.y; p4[qi][2] = pv.z; p4[qi][3] = pv.w;
        }
        #pragma unroll
        for (int u = 0; u < 4; u++) {
            int z = z4 + u;
            float vj[4];
            #pragma unroll
            for (int j = 0; j < 4; j++) vj[j] = Vsh[z*KSTR + l + 32*j];
            #pragma unroll
            for (int qi = 0; qi < 4; qi++)
                #pragma unroll
                for (int j = 0; j < 4; j++) o[qi][j] += p4[qi][u] * vj[j];
        }
    }
    float* sob = g_so + ((size_t)b*NSL + (size_t)c*BS)*D;
    #pragma unroll
    for (int qi = 0; qi < 4; qi++)
        #pragma unroll
        for (int j = 0; j < 4; j++)
            sob[(w*4 + qi)*D + l + 32*j] = o[qi][j];
}

// ---------------- K4: unsort + cross-hash softmax combine ----------------
// grid 4096, block 256 (warp per token)
__global__ __launch_bounds__(256) void k4_combine(float* __restrict__ out) {
    int tid = threadIdx.x, w = tid >> 5, l = tid & 31;
    int token = blockIdx.x*8 + w;          // 0..32767
    int b = token >> 12, s = token & (SL - 1);

    int slotl = 0; float lsel = -FLT_MAX;
    if (l < NH) { slotl = g_slotof[b][l][s]; lsel = g_slse[b][slotl]; }
    int slot[NH]; float lse[NH];
    #pragma unroll
    for (int h = 0; h < NH; h++) {
        slot[h] = __shfl_sync(0xffffffffu, slotl, h);
        lse[h]  = __shfl_sync(0xffffffffu, lsel,  h);
    }
    float m = -FLT_MAX;
    #pragma unroll
    for (int h = 0; h < NH; h++) m = fmaxf(m, lse[h]);
    float Z = 0.f;
    #pragma unroll
    for (int h = 0; h < NH; h++) Z += expf(lse[h] - m);
    float invZ = 1.f / Z;

    float4 acc = make_float4(0.f, 0.f, 0.f, 0.f);
    #pragma unroll
    for (int h = 0; h < NH; h++) {
        float wgt = expf(lse[h] - m) * invZ;
        float4 r = *(const float4*)(g_so + ((size_t)b*NSL + (size_t)slot[h])*D + 4*l);
        acc.x += wgt*r.x; acc.y += wgt*r.y; acc.z += wgt*r.z; acc.w += wgt*r.w;
    }
    *((float4*)(out + ((size_t)b*SL + (size_t)s)*D + 4*l)) = acc;
}

// ---------------- launcher ----------------
extern "C" void kernel_launch(void* const* d_in, const int* in_sizes, int n_in,
                              void* d_out, int out_size) {
    const float* qk  = (const float*)d_in[0];
    const float* v   = (const float*)d_in[1];
    const float* rot = (const float*)d_in[2];
    float* out = (float*)d_out;

    const int smem3 = (128*KSTR*2 + 64*D*2) * 4 + 128*4 + 128*9*4;  // 202752 B
    cudaFuncSetAttribute(k3_attn, cudaFuncAttributeMaxDynamicSharedMemorySize, smem3);

    k1_buckets<<<dim3(128, NH, NBATCH), 256>>>(qk, rot);
    k2_sort  <<<dim3(NH, NBATCH), 256>>>();
    k3_attn  <<<dim3(NC, NBATCH), 512, smem3>>>(qk, v);
    k4_combine<<<dim3(4096), 256>>>(out);
}

// round 4
// speedup vs baseline: 1.1398x; 1.1398x over previous
#include <cuda_runtime.h>
#include <math.h>
#include <float.h>

#define NBATCH 8
#define SL 4096
#define D 128
#define NH 8
#define NB 64        // buckets per hash
#define BS 64        // bucket/chunk size
#define NC 512       // total chunks per batch (NH * NB)
#define NSL (NH*SL)  // 32768 sorted slots per batch
#define KSTR 130     // smem row stride (floats): even -> 8B-aligned LDS.64, conflict-free
#define PSTR 66      // Pt row stride (floats)
#define LSTR 9       // lut row stride (u64) -> conflict-free LDS.64
#define SCALE 0.08838834764831845f  // 128^-0.5

typedef unsigned long long u64;

__device__ __forceinline__ u64 fma2(u64 a, u64 b, u64 c) {
    u64 d; asm("fma.rn.f32x2 %0, %1, %2, %3;" : "=l"(d) : "l"(a), "l"(b), "l"(c)); return d;
}
__device__ __forceinline__ u64 pack2(float lo, float hi) {
    u64 d; asm("mov.b64 %0, {%1, %2};" : "=l"(d) : "f"(lo), "f"(hi)); return d;
}
__device__ __forceinline__ float2 unpack2(u64 v) {
    float2 r; asm("mov.b64 {%0, %1}, %2;" : "=f"(r.x), "=f"(r.y) : "l"(v)); return r;
}

// ---------------- scratch ----------------
__device__ unsigned char g_bkt[NBATCH][NH][SL];
__device__ int           g_st[NBATCH][NSL];
__device__ int           g_slotof[NBATCH][NH][SL];
__device__ unsigned      g_locs[NBATCH][SL*NH];
__device__ float         g_slse[NBATCH][NSL];
__device__ float         g_so[(size_t)NBATCH*NSL*D];

// ---------------- K1: LSH bucket assignment (FFMA2, transposed rot tile) ----------------
// grid (128, NH, NBATCH), block 256. Block: 32 tokens for one (b,h).
__global__ __launch_bounds__(256) void k1_buckets(const float* __restrict__ qk,
                                                  const float* __restrict__ rot) {
    __shared__ float rotT[32*KSTR];   // [n][d]
    __shared__ float qrows[32*KSTR];  // [r][d]
    int stile = blockIdx.x, h = blockIdx.y, b = blockIdx.z;
    int tid = threadIdx.x, w = tid >> 5, l = tid & 31;

    for (int i = tid; i < 32*D; i += 256) {
        int n = i & 31, d = i >> 5;
        rotT[n*KSTR + d] = rot[d*(NH*32) + h*32 + n];
    }
    const float* qb = qk + ((size_t)b*SL + (size_t)stile*32)*D;
    for (int i = tid; i < 32*D; i += 256) {
        int r = i >> 7, d = i & 127;
        qrows[r*KSTR + d] = qb[r*D + d];
    }
    __syncthreads();

    u64 acc2[4] = {0ull,0ull,0ull,0ull};
    for (int d = 0; d < D; d += 4) {
        u64 ra = *(const u64*)(rotT + l*KSTR + d);
        u64 rb = *(const u64*)(rotT + l*KSTR + d + 2);
        #pragma unroll
        for (int r = 0; r < 4; r++) {
            u64 qa  = *(const u64*)(qrows + (w*4 + r)*KSTR + d);
            u64 qb2 = *(const u64*)(qrows + (w*4 + r)*KSTR + d + 2);
            acc2[r] = fma2(qa, ra, acc2[r]);
            acc2[r] = fma2(qb2, rb, acc2[r]);
        }
    }
    #pragma unroll
    for (int r = 0; r < 4; r++) {
        float2 p = unpack2(acc2[r]);
        float a = p.x + p.y;
        float bv = a; int bi = l;
        if (-a > bv) { bv = -a; bi = l + 32; }
        #pragma unroll
        for (int off = 16; off > 0; off >>= 1) {
            float ov = __shfl_xor_sync(0xffffffffu, bv, off);
            int   oi = __shfl_xor_sync(0xffffffffu, bi, off);
            if (ov > bv || (ov == bv && oi < bi)) { bv = ov; bi = oi; }
        }
        if (l == 0) g_bkt[b][h][stile*32 + w*4 + r] = (unsigned char)bi;
    }
}

// ---------------- K2: stable counting sort per (b,h) ----------------
__global__ __launch_bounds__(256) void k2_sort() {
    __shared__ unsigned char  bkt[SL];
    __shared__ unsigned short cnt[NB*257];
    __shared__ int tot[NB];
    __shared__ int base[NB];
    int h = blockIdx.x, b = blockIdx.y;
    int t = threadIdx.x;

    ((int4*)bkt)[t] = ((const int4*)&g_bkt[b][h][0])[t];
    for (int i = t; i < NB*257; i += 256) cnt[i] = 0;
    __syncthreads();

    #pragma unroll
    for (int j = 0; j < 16; j++) {
        int c = bkt[t*16 + j];
        cnt[c*257 + t]++;
    }
    __syncthreads();

    if (t < NB) {
        int run = 0;
        for (int i = 0; i < 256; i++) {
            int v = cnt[t*257 + i];
            cnt[t*257 + i] = (unsigned short)run;
            run += v;
        }
        tot[t] = run;
    }
    __syncthreads();
    if (t == 0) {
        int run = 0;
        for (int c = 0; c < NB; c++) { base[c] = run; run += tot[c]; }
    }
    __syncthreads();

    #pragma unroll
    for (int j = 0; j < 16; j++) {
        int i = t*16 + j;
        int c = bkt[i];
        int r = cnt[c*257 + t]++;
        int slot = h*SL + base[c] + r;
        g_st[b][slot] = i;
        g_slotof[b][h][i] = slot;
        g_locs[b][i*NH + h] = (unsigned)(((h*NB + c) << 9) | (slot >> 6));
    }
}

// ---------------- K3: chunked attention (FFMA2 GEMMs) ----------------
// grid (NC, NBATCH), block 256 (8 warps), ~177KB smem, 1 CTA/SM.
__global__ __launch_bounds__(256) void k3_attn(const float* __restrict__ qk,
                                               const float* __restrict__ vglob) {
    extern __shared__ char smraw[];
    u64*   lut = (u64*)smraw;                       // [128][LSTR] lo=lk, hi=lk2
    float* Ksh = (float*)(smraw + 128*LSTR*8);      // [128][KSTR] normalized rows
    float* Vsh = Ksh + 128*KSTR;                    // [128][KSTR]
    float* Pt  = Vsh + 128*KSTR;                    // [128][PSTR] transposed probs
    float* nrm = Pt + 128*PSTR;                     // [64] query norms
    int*   stk = (int*)(nrm + 64);                  // [128]

    int c = blockIdx.x, b = blockIdx.y;
    int cprev = (c + NC - 1) % NC;
    int tid = threadIdx.x, w = tid >> 5, l = tid & 31;
    int qbase = w * 8;

    if (tid < 128)
        stk[tid] = g_st[b][(tid < 64 ? c : cprev)*BS + (tid & 63)];
    __syncthreads();

    // locs table: (lk, lk2) packed per (token, hash)
    for (int i = tid; i < 128*NH; i += 256) {
        int z = i >> 3, hh = i & 7;
        unsigned lk = g_locs[b][stk[z]*NH + hh];
        unsigned lk2 = (lk & ~511u) | ((lk + 1u) & 511u);
        lut[z*LSTR + hh] = ((u64)lk2 << 32) | (u64)lk;
    }

    // gather + normalize
    const float* qkb = qk    + (size_t)b*SL*D;
    const float* vb  = vglob + (size_t)b*SL*D;
    #pragma unroll 4
    for (int i = 0; i < 16; i++) {
        int r = w + 8*i;
        int tok = stk[r];
        float4 kv = ((const float4*)(qkb + (size_t)tok*D))[l];
        float ss = kv.x*kv.x + kv.y*kv.y + kv.z*kv.z + kv.w*kv.w;
        #pragma unroll
        for (int off = 16; off > 0; off >>= 1) ss += __shfl_xor_sync(0xffffffffu, ss, off);
        float nn = fmaxf(sqrtf(ss), 1e-12f);
        float rn = 1.0f / nn;
        *(u64*)(Ksh + r*KSTR + 4*l)     = pack2(kv.x*rn, kv.y*rn);
        *(u64*)(Ksh + r*KSTR + 4*l + 2) = pack2(kv.z*rn, kv.w*rn);
        float4 vv = ((const float4*)(vb + (size_t)tok*D))[l];
        *(u64*)(Vsh + r*KSTR + 4*l)     = pack2(vv.x, vv.y);
        *(u64*)(Vsh + r*KSTR + 4*l + 2) = pack2(vv.z, vv.w);
        if (r < 64 && l == 0) nrm[r] = nn;
    }
    __syncthreads();

    // ---- QK^T: thread tile 8q x 4z, f32x2 packed along d ----
    u64 a2[8][4];
    #pragma unroll
    for (int qi = 0; qi < 8; qi++)
        #pragma unroll
        for (int j = 0; j < 4; j++) a2[qi][j] = 0ull;

    for (int d = 0; d < D; d += 4) {
        u64 ka[4], kb[4];
        #pragma unroll
        for (int j = 0; j < 4; j++) {
            const float* kp = Ksh + (l + 32*j)*KSTR + d;
            ka[j] = *(const u64*)kp;
            kb[j] = *(const u64*)(kp + 2);
        }
        #pragma unroll
        for (int qi = 0; qi < 8; qi++) {
            const float* qp = Ksh + (qbase + qi)*KSTR + d;
            u64 qa  = *(const u64*)qp;
            u64 qb2 = *(const u64*)(qp + 2);
            #pragma unroll
            for (int j = 0; j < 4; j++) {
                a2[qi][j] = fma2(qa,  ka[j], a2[qi][j]);
                a2[qi][j] = fma2(qb2, kb[j], a2[qi][j]);
            }
        }
    }

    float val[8][4];
    #pragma unroll
    for (int qi = 0; qi < 8; qi++)
        #pragma unroll
        for (int j = 0; j < 4; j++) {
            float2 p = unpack2(a2[qi][j]);
            val[qi][j] = p.x + p.y;
        }

    // ---- masks + duplicate-count correction ----
    int hq = c >> 6, hkp = cprev >> 6;
    int tk[4]; unsigned bk[4];
    #pragma unroll
    for (int j = 0; j < 4; j++) {
        int z = l + 32*j;
        tk[j] = stk[z];
        bk[j] = ((unsigned)lut[z*LSTR + (j < 2 ? hq : hkp)]) >> 9;
    }

    int cdup[8][4];
    #pragma unroll
    for (int qi = 0; qi < 8; qi++)
        #pragma unroll
        for (int j = 0; j < 4; j++) cdup[qi][j] = 0;

    #pragma unroll
    for (int hh = 0; hh < NH; hh++) {
        unsigned lq[8];
        #pragma unroll
        for (int qi = 0; qi < 8; qi++) lq[qi] = (unsigned)lut[(qbase + qi)*LSTR + hh];
        #pragma unroll
        for (int j = 0; j < 4; j++) {
            u64 pr = lut[(l + 32*j)*LSTR + hh];
            unsigned lk = (unsigned)pr, lk2 = (unsigned)(pr >> 32);
            #pragma unroll
            for (int qi = 0; qi < 8; qi++)
                cdup[qi][j] += (int)((lq[qi] == lk) | (lq[qi] == lk2));
        }
    }

    // ---- masks, softmax per q row, store Pt transposed ----
    #pragma unroll
    for (int qi = 0; qi < 8; qi++) {
        int q = qbase + qi;
        int tq = stk[q];
        unsigned bq = ((unsigned)lut[q*LSTR + hq]) >> 9;
        float nq = nrm[q] * SCALE;
        #pragma unroll
        for (int j = 0; j < 4; j++) {
            float v = val[qi][j] * nq;
            if (tq <  tk[j]) v = -FLT_MAX;
            if (tq == tk[j]) v = -10000.0f;
            if (bq != bk[j]) v = -FLT_MAX;
            v -= __logf((float)cdup[qi][j] + 1e-9f);
            val[qi][j] = v;
        }
        float m = fmaxf(fmaxf(val[qi][0], val[qi][1]), fmaxf(val[qi][2], val[qi][3]));
        #pragma unroll
        for (int off = 16; off > 0; off >>= 1) m = fmaxf(m, __shfl_xor_sync(0xffffffffu, m, off));
        float s_ = 0.f;
        #pragma unroll
        for (int j = 0; j < 4; j++) s_ += __expf(val[qi][j] - m);
        #pragma unroll
        for (int off = 16; off > 0; off >>= 1) s_ += __shfl_xor_sync(0xffffffffu, s_, off);
        float lse = m + __logf(s_);
        if (l == 0) g_slse[b][c*BS + q] = lse;
        #pragma unroll
        for (int j = 0; j < 4; j++)
            val[qi][j] = __expf(val[qi][j] - lse);
    }
    #pragma unroll
    for (int qp = 0; qp < 4; qp++)
        #pragma unroll
        for (int j = 0; j < 4; j++)
            *(u64*)(Pt + (l + 32*j)*PSTR + qbase + 2*qp) = pack2(val[2*qp][j], val[2*qp + 1][j]);
    __syncthreads();

    // ---- P*V: thread tile 8q x 4dcol, f32x2 packed along q-pairs ----
    u64 o2[4][4];
    #pragma unroll
    for (int qp = 0; qp < 4; qp++)
        #pragma unroll
        for (int j = 0; j < 4; j++) o2[qp][j] = 0ull;

    for (int z = 0; z < 128; z++) {
        float2 v01 = *(const float2*)(Vsh + z*KSTR + 2*l);
        float2 v23 = *(const float2*)(Vsh + z*KSTR + 2*l + 64);
        u64 vv0 = pack2(v01.x, v01.x);
        u64 vv1 = pack2(v01.y, v01.y);
        u64 vv2 = pack2(v23.x, v23.x);
        u64 vv3 = pack2(v23.y, v23.y);
        #pragma unroll
        for (int qp = 0; qp < 4; qp++) {
            u64 p2 = *(const u64*)(Pt + z*PSTR + qbase + 2*qp);
            o2[qp][0] = fma2(p2, vv0, o2[qp][0]);
            o2[qp][1] = fma2(p2, vv1, o2[qp][1]);
            o2[qp][2] = fma2(p2, vv2, o2[qp][2]);
            o2[qp][3] = fma2(p2, vv3, o2[qp][3]);
        }
    }

    float* sob = g_so + ((size_t)b*NSL + (size_t)c*BS)*D;
    #pragma unroll
    for (int qp = 0; qp < 4; qp++) {
        float2 a0 = unpack2(o2[qp][0]);
        float2 a1 = unpack2(o2[qp][1]);
        float2 c2 = unpack2(o2[qp][2]);
        float2 c3 = unpack2(o2[qp][3]);
        int qe = qbase + 2*qp, qo = qe + 1;
        *(float2*)(sob + qe*D + 2*l)      = make_float2(a0.x, a1.x);
        *(float2*)(sob + qo*D + 2*l)      = make_float2(a0.y, a1.y);
        *(float2*)(sob + qe*D + 2*l + 64) = make_float2(c2.x, c3.x);
        *(float2*)(sob + qo*D + 2*l + 64) = make_float2(c2.y, c3.y);
    }
}

// ---------------- K4: unsort + cross-hash softmax combine ----------------
__global__ __launch_bounds__(256) void k4_combine(float* __restrict__ out) {
    int tid = threadIdx.x, w = tid >> 5, l = tid & 31;
    int token = blockIdx.x*8 + w;
    int b = token >> 12, s = token & (SL - 1);

    int slotl = 0; float lsel = -FLT_MAX;
    if (l < NH) { slotl = g_slotof[b][l][s]; lsel = g_slse[b][slotl]; }
    int slot[NH]; float lse[NH];
    #pragma unroll
    for (int h = 0; h < NH; h++) {
        slot[h] = __shfl_sync(0xffffffffu, slotl, h);
        lse[h]  = __shfl_sync(0xffffffffu, lsel,  h);
    }
    float m = -FLT_MAX;
    #pragma unroll
    for (int h = 0; h < NH; h++) m = fmaxf(m, lse[h]);
    float Z = 0.f;
    #pragma unroll
    for (int h = 0; h < NH; h++) Z += __expf(lse[h] - m);
    float invZ = 1.f / Z;

    float4 acc = make_float4(0.f, 0.f, 0.f, 0.f);
    #pragma unroll
    for (int h = 0; h < NH; h++) {
        float wgt = __expf(lse[h] - m) * invZ;
        float4 r = *(const float4*)(g_so + ((size_t)b*NSL + (size_t)slot[h])*D + 4*l);
        acc.x += wgt*r.x; acc.y += wgt*r.y; acc.z += wgt*r.z; acc.w += wgt*r.w;
    }
    *((float4*)(out + ((size_t)b*SL + (size_t)s)*D + 4*l)) = acc;
}

// ---------------- launcher ----------------
extern "C" void kernel_launch(void* const* d_in, const int* in_sizes, int n_in,
                              void* d_out, int out_size) {
    const float* qk  = (const float*)d_in[0];
    const float* v   = (const float*)d_in[1];
    const float* rot = (const float*)d_in[2];
    float* out = (float*)d_out;

    const int smem3 = 128*LSTR*8 + (128*KSTR*2 + 128*PSTR + 64)*4 + 128*4;  // 176896 B
    cudaFuncSetAttribute(k3_attn, cudaFuncAttributeMaxDynamicSharedMemorySize, smem3);

    k1_buckets<<<dim3(128, NH, NBATCH), 256>>>(qk, rot);
    k2_sort  <<<dim3(NH, NBATCH), 256>>>();
    k3_attn  <<<dim3(NC, NBATCH), 256, smem3>>>(qk, v);
    k4_combine<<<dim3(4096), 256>>>(out);
}

// round 5
// speedup vs baseline: 1.2603x; 1.1057x over previous
#include <cuda_runtime.h>
#include <math.h>
#include <float.h>

#define NBATCH 8
#define SL 4096
#define D 128
#define NH 8
#define NB 64        // buckets per hash
#define BS 64        // bucket/chunk size
#define NC 512       // total chunks per batch (NH * NB)
#define NSL (NH*SL)  // 32768 sorted slots per batch
#define KSTR 132     // smem row stride (floats): ≡4 mod 8 -> conflict-free cross-row LDS.128
#define PSTR 66      // Pt row stride (floats)
#define LSTR 9       // lut row stride (u64) -> conflict-free LDS.64
#define SCALE 0.08838834764831845f  // 128^-0.5

typedef unsigned long long u64;

__device__ __forceinline__ u64 fma2(u64 a, u64 b, u64 c) {
    u64 d; asm("fma.rn.f32x2 %0, %1, %2, %3;" : "=l"(d) : "l"(a), "l"(b), "l"(c)); return d;
}
__device__ __forceinline__ u64 pack2(float lo, float hi) {
    u64 d; asm("mov.b64 %0, {%1, %2};" : "=l"(d) : "f"(lo), "f"(hi)); return d;
}
__device__ __forceinline__ float2 unpack2(u64 v) {
    float2 r; asm("mov.b64 {%0, %1}, %2;" : "=f"(r.x), "=f"(r.y) : "l"(v)); return r;
}

// ---------------- scratch ----------------
__device__ unsigned char g_bkt[NBATCH][NH][SL];
__device__ int           g_st[NBATCH][NSL];
__device__ int           g_slotof[NBATCH][NH][SL];
__device__ unsigned      g_locs[NBATCH][SL*NH];
__device__ float         g_slse[NBATCH][NSL];
__device__ float         g_so[(size_t)NBATCH*NSL*D];

// ---------------- K1: LSH bucket assignment ----------------
__global__ __launch_bounds__(256) void k1_buckets(const float* __restrict__ qk,
                                                  const float* __restrict__ rot) {
    __shared__ float rotT[32*KSTR];   // [n][d]
    __shared__ float qrows[32*KSTR];  // [r][d]
    int stile = blockIdx.x, h = blockIdx.y, b = blockIdx.z;
    int tid = threadIdx.x, w = tid >> 5, l = tid & 31;

    for (int i = tid; i < 32*D; i += 256) {
        int n = i & 31, d = i >> 5;
        rotT[n*KSTR + d] = rot[d*(NH*32) + h*32 + n];
    }
    const float* qb = qk + ((size_t)b*SL + (size_t)stile*32)*D;
    for (int i = tid; i < 32*D; i += 256) {
        int r = i >> 7, d = i & 127;
        qrows[r*KSTR + d] = qb[r*D + d];
    }
    __syncthreads();

    u64 acc2[4] = {0ull,0ull,0ull,0ull};
    for (int d = 0; d < D; d += 4) {
        ulonglong2 rr = *(const ulonglong2*)(rotT + l*KSTR + d);
        #pragma unroll
        for (int r = 0; r < 4; r++) {
            ulonglong2 qq = *(const ulonglong2*)(qrows + (w*4 + r)*KSTR + d);
            acc2[r] = fma2(qq.x, rr.x, acc2[r]);
            acc2[r] = fma2(qq.y, rr.y, acc2[r]);
        }
    }
    #pragma unroll
    for (int r = 0; r < 4; r++) {
        float2 p = unpack2(acc2[r]);
        float a = p.x + p.y;
        float bv = a; int bi = l;
        if (-a > bv) { bv = -a; bi = l + 32; }
        #pragma unroll
        for (int off = 16; off > 0; off >>= 1) {
            float ov = __shfl_xor_sync(0xffffffffu, bv, off);
            int   oi = __shfl_xor_sync(0xffffffffu, bi, off);
            if (ov > bv || (ov == bv && oi < bi)) { bv = ov; bi = oi; }
        }
        if (l == 0) g_bkt[b][h][stile*32 + w*4 + r] = (unsigned char)bi;
    }
}

// ---------------- K2: stable counting sort per (b,h) ----------------
__global__ __launch_bounds__(256) void k2_sort() {
    __shared__ unsigned char  bkt[SL];
    __shared__ unsigned short cnt[NB*257];
    __shared__ int tot[NB];
    __shared__ int base[NB];
    int h = blockIdx.x, b = blockIdx.y;
    int t = threadIdx.x;

    ((int4*)bkt)[t] = ((const int4*)&g_bkt[b][h][0])[t];
    for (int i = t; i < NB*257; i += 256) cnt[i] = 0;
    __syncthreads();

    #pragma unroll
    for (int j = 0; j < 16; j++) {
        int c = bkt[t*16 + j];
        cnt[c*257 + t]++;
    }
    __syncthreads();

    if (t < NB) {
        int run = 0;
        for (int i = 0; i < 256; i++) {
            int v = cnt[t*257 + i];
            cnt[t*257 + i] = (unsigned short)run;
            run += v;
        }
        tot[t] = run;
    }
    __syncthreads();
    if (t == 0) {
        int run = 0;
        for (int c = 0; c < NB; c++) { base[c] = run; run += tot[c]; }
    }
    __syncthreads();

    #pragma unroll
    for (int j = 0; j < 16; j++) {
        int i = t*16 + j;
        int c = bkt[i];
        int r = cnt[c*257 + t]++;
        int slot = h*SL + base[c] + r;
        g_st[b][slot] = i;
        g_slotof[b][h][i] = slot;
        g_locs[b][i*NH + h] = (unsigned)(((h*NB + c) << 9) | (slot >> 6));
    }
}

// ---------------- K3: chunked attention (512 threads, FFMA2, LDS.128) ----------------
// grid (NC, NBATCH), block 512 (16 warps), ~179KB smem, 1 CTA/SM.
__global__ __launch_bounds__(512, 1) void k3_attn(const float* __restrict__ qk,
                                                  const float* __restrict__ vglob) {
    extern __shared__ char smraw[];
    u64*   lut = (u64*)smraw;                       // [128][LSTR] lo=lk, hi=lk2
    float* Ksh = (float*)(smraw + 128*LSTR*8);      // [128][KSTR] normalized rows
    float* Vsh = Ksh + 128*KSTR;                    // [128][KSTR]
    float* Pt  = Vsh + 128*KSTR;                    // [128][PSTR] transposed probs
    float* nrm = Pt + 128*PSTR;                     // [64] query norms
    int*   stk = (int*)(nrm + 64);                  // [128]

    int c = blockIdx.x, b = blockIdx.y;
    int cprev = (c + NC - 1) % NC;
    int tid = threadIdx.x, w = tid >> 5, l = tid & 31;
    int qbase = w * 4;                              // warp owns q rows 4w..4w+3

    if (tid < 128)
        stk[tid] = g_st[b][(tid < 64 ? c : cprev)*BS + (tid & 63)];
    __syncthreads();

    // locs table: (lk, lk2) packed per (token, hash)
    for (int i = tid; i < 128*NH; i += 512) {
        int z = i >> 3, hh = i & 7;
        unsigned lk = g_locs[b][stk[z]*NH + hh];
        unsigned lk2 = (lk & ~511u) | ((lk + 1u) & 511u);
        lut[z*LSTR + hh] = ((u64)lk2 << 32) | (u64)lk;
    }

    // gather + normalize: warp w handles rows w, w+16, ...
    const float* qkb = qk    + (size_t)b*SL*D;
    const float* vb  = vglob + (size_t)b*SL*D;
    #pragma unroll
    for (int i = 0; i < 8; i++) {
        int r = w + 16*i;
        int tok = stk[r];
        float4 kv = ((const float4*)(qkb + (size_t)tok*D))[l];
        float ss = kv.x*kv.x + kv.y*kv.y + kv.z*kv.z + kv.w*kv.w;
        #pragma unroll
        for (int off = 16; off > 0; off >>= 1) ss += __shfl_xor_sync(0xffffffffu, ss, off);
        float nn = fmaxf(sqrtf(ss), 1e-12f);
        float rn = 1.0f / nn;
        *(float4*)(Ksh + r*KSTR + 4*l) = make_float4(kv.x*rn, kv.y*rn, kv.z*rn, kv.w*rn);
        float4 vv = ((const float4*)(vb + (size_t)tok*D))[l];
        *(float4*)(Vsh + r*KSTR + 4*l) = vv;
        if (r < 64 && l == 0) nrm[r] = nn;
    }
    __syncthreads();

    // ---- QK^T: thread tile 4q x 4z (z = l+32j), f32x2 packed along d ----
    u64 a2[4][4];
    #pragma unroll
    for (int qi = 0; qi < 4; qi++)
        #pragma unroll
        for (int j = 0; j < 4; j++) a2[qi][j] = 0ull;

    for (int d = 0; d < D; d += 4) {
        ulonglong2 kk[4];
        #pragma unroll
        for (int j = 0; j < 4; j++)
            kk[j] = *(const ulonglong2*)(Ksh + (l + 32*j)*KSTR + d);
        #pragma unroll
        for (int qi = 0; qi < 4; qi++) {
            ulonglong2 qq = *(const ulonglong2*)(Ksh + (qbase + qi)*KSTR + d);  // broadcast
            #pragma unroll
            for (int j = 0; j < 4; j++) {
                a2[qi][j] = fma2(qq.x, kk[j].x, a2[qi][j]);
                a2[qi][j] = fma2(qq.y, kk[j].y, a2[qi][j]);
            }
        }
    }

    float val[4][4];
    #pragma unroll
    for (int qi = 0; qi < 4; qi++)
        #pragma unroll
        for (int j = 0; j < 4; j++) {
            float2 p = unpack2(a2[qi][j]);
            val[qi][j] = p.x + p.y;
        }

    // ---- masks + duplicate-count correction ----
    int hq = c >> 6, hkp = cprev >> 6;
    int tk[4]; unsigned bk[4];
    #pragma unroll
    for (int j = 0; j < 4; j++) {
        int z = l + 32*j;
        tk[j] = stk[z];
        bk[j] = ((unsigned)lut[z*LSTR + (j < 2 ? hq : hkp)]) >> 9;
    }

    int cdup[4][4];
    #pragma unroll
    for (int qi = 0; qi < 4; qi++)
        #pragma unroll
        for (int j = 0; j < 4; j++) cdup[qi][j] = 0;

    #pragma unroll
    for (int hh = 0; hh < NH; hh++) {
        unsigned lq[4];
        #pragma unroll
        for (int qi = 0; qi < 4; qi++) lq[qi] = (unsigned)lut[(qbase + qi)*LSTR + hh];
        #pragma unroll
        for (int j = 0; j < 4; j++) {
            u64 pr = lut[(l + 32*j)*LSTR + hh];
            unsigned lk = (unsigned)pr, lk2 = (unsigned)(pr >> 32);
            #pragma unroll
            for (int qi = 0; qi < 4; qi++)
                cdup[qi][j] += (int)((lq[qi] == lk) | (lq[qi] == lk2));
        }
    }

    // ---- masks, softmax per q row, store Pt transposed ----
    #pragma unroll
    for (int qi = 0; qi < 4; qi++) {
        int q = qbase + qi;
        int tq = stk[q];
        unsigned bq = ((unsigned)lut[q*LSTR + hq]) >> 9;
        float nq = nrm[q] * SCALE;
        #pragma unroll
        for (int j = 0; j < 4; j++) {
            float v = val[qi][j] * nq;
            if (tq <  tk[j]) v = -FLT_MAX;
            if (tq == tk[j]) v = -10000.0f;
            if (bq != bk[j]) v = -FLT_MAX;
            v -= __logf((float)cdup[qi][j] + 1e-9f);
            val[qi][j] = v;
        }
        float m = fmaxf(fmaxf(val[qi][0], val[qi][1]), fmaxf(val[qi][2], val[qi][3]));
        #pragma unroll
        for (int off = 16; off > 0; off >>= 1) m = fmaxf(m, __shfl_xor_sync(0xffffffffu, m, off));
        float s_ = 0.f;
        #pragma unroll
        for (int j = 0; j < 4; j++) s_ += __expf(val[qi][j] - m);
        #pragma unroll
        for (int off = 16; off > 0; off >>= 1) s_ += __shfl_xor_sync(0xffffffffu, s_, off);
        float lse = m + __logf(s_);
        if (l == 0) g_slse[b][c*BS + q] = lse;
        #pragma unroll
        for (int j = 0; j < 4; j++)
            val[qi][j] = __expf(val[qi][j] - lse);
    }
    #pragma unroll
    for (int j = 0; j < 4; j++) {
        int z = l + 32*j;
        *(u64*)(Pt + z*PSTR + qbase)     = pack2(val[0][j], val[1][j]);
        *(u64*)(Pt + z*PSTR + qbase + 2) = pack2(val[2][j], val[3][j]);
    }
    __syncthreads();

    // ---- P*V: thread tile 4q x 4dcol (cols 4l..4l+3), f32x2 packed along q-pairs ----
    u64 o2[2][4];
    #pragma unroll
    for (int qp = 0; qp < 2; qp++)
        #pragma unroll
        for (int cc = 0; cc < 4; cc++) o2[qp][cc] = 0ull;

    for (int z = 0; z < 128; z++) {
        float4 vv = *(const float4*)(Vsh + z*KSTR + 4*l);   // conflict-free LDS.128
        u64 p0 = *(const u64*)(Pt + z*PSTR + qbase);        // broadcast
        u64 p1 = *(const u64*)(Pt + z*PSTR + qbase + 2);
        u64 v0 = pack2(vv.x, vv.x), v1 = pack2(vv.y, vv.y);
        u64 v2 = pack2(vv.z, vv.z), v3 = pack2(vv.w, vv.w);
        o2[0][0] = fma2(p0, v0, o2[0][0]);
        o2[0][1] = fma2(p0, v1, o2[0][1]);
        o2[0][2] = fma2(p0, v2, o2[0][2]);
        o2[0][3] = fma2(p0, v3, o2[0][3]);
        o2[1][0] = fma2(p1, v0, o2[1][0]);
        o2[1][1] = fma2(p1, v1, o2[1][1]);
        o2[1][2] = fma2(p1, v2, o2[1][2]);
        o2[1][3] = fma2(p1, v3, o2[1][3]);
    }

    float* sob = g_so + ((size_t)b*NSL + (size_t)c*BS)*D;
    #pragma unroll
    for (int qp = 0; qp < 2; qp++) {
        float2 c0 = unpack2(o2[qp][0]);
        float2 c1 = unpack2(o2[qp][1]);
        float2 c2 = unpack2(o2[qp][2]);
        float2 c3 = unpack2(o2[qp][3]);
        int qe = qbase + 2*qp, qo = qe + 1;
        *(float4*)(sob + qe*D + 4*l) = make_float4(c0.x, c1.x, c2.x, c3.x);
        *(float4*)(sob + qo*D + 4*l) = make_float4(c0.y, c1.y, c2.y, c3.y);
    }
}

// ---------------- K4: unsort + cross-hash softmax combine ----------------
__global__ __launch_bounds__(256) void k4_combine(float* __restrict__ out) {
    int tid = threadIdx.x, w = tid >> 5, l = tid & 31;
    int token = blockIdx.x*8 + w;
    int b = token >> 12, s = token & (SL - 1);

    int slotl = 0; float lsel = -FLT_MAX;
    if (l < NH) { slotl = g_slotof[b][l][s]; lsel = g_slse[b][slotl]; }
    int slot[NH]; float lse[NH];
    #pragma unroll
    for (int h = 0; h < NH; h++) {
        slot[h] = __shfl_sync(0xffffffffu, slotl, h);
        lse[h]  = __shfl_sync(0xffffffffu, lsel,  h);
    }
    float m = -FLT_MAX;
    #pragma unroll
    for (int h = 0; h < NH; h++) m = fmaxf(m, lse[h]);
    float Z = 0.f;
    #pragma unroll
    for (int h = 0; h < NH; h++) Z += __expf(lse[h] - m);
    float invZ = 1.f / Z;

    float4 acc = make_float4(0.f, 0.f, 0.f, 0.f);
    #pragma unroll
    for (int h = 0; h < NH; h++) {
        float wgt = __expf(lse[h] - m) * invZ;
        float4 r = *(const float4*)(g_so + ((size_t)b*NSL + (size_t)slot[h])*D + 4*l);
        acc.x += wgt*r.x; acc.y += wgt*r.y; acc.z += wgt*r.z; acc.w += wgt*r.w;
    }
    *((float4*)(out + ((size_t)b*SL + (size_t)s)*D + 4*l)) = acc;
}

// ---------------- launcher ----------------
extern "C" void kernel_launch(void* const* d_in, const int* in_sizes, int n_in,
                              void* d_out, int out_size) {
    const float* qk  = (const float*)d_in[0];
    const float* v   = (const float*)d_in[1];
    const float* rot = (const float*)d_in[2];
    float* out = (float*)d_out;

    const int smem3 = 128*LSTR*8 + (128*KSTR*2 + 128*PSTR + 64)*4 + 128*4;  // 178944 B
    cudaFuncSetAttribute(k3_attn, cudaFuncAttributeMaxDynamicSharedMemorySize, smem3);

    k1_buckets<<<dim3(128, NH, NBATCH), 256>>>(qk, rot);
    k2_sort  <<<dim3(NH, NBATCH), 256>>>();
    k3_attn  <<<dim3(NC, NBATCH), 512, smem3>>>(qk, v);
    k4_combine<<<dim3(4096), 256>>>(out);
}

// round 6
// speedup vs baseline: 1.3525x; 1.0732x over previous
#include <cuda_runtime.h>
#include <math.h>
#include <float.h>

#define NBATCH 8
#define SL 4096
#define D 128
#define NH 8
#define NB 64        // buckets per hash
#define BS 64        // bucket/chunk size
#define NC 512       // total chunks per batch (NH * NB)
#define NSL (NH*SL)  // 32768 sorted slots per batch
#define KSTR 132     // smem row stride (floats): ≡4 mod 8 -> conflict-free cross-row LDS.128
#define PSTR 68      // Pt row stride (floats): mult of 4 -> conflict-free STS.128
#define LSTR 9       // lut row stride (u64)
#define SCALE 0.08838834764831845f  // 128^-0.5

typedef unsigned long long u64;

__device__ __forceinline__ u64 fma2(u64 a, u64 b, u64 c) {
    u64 d; asm("fma.rn.f32x2 %0, %1, %2, %3;" : "=l"(d) : "l"(a), "l"(b), "l"(c)); return d;
}
__device__ __forceinline__ u64 pack2(float lo, float hi) {
    u64 d; asm("mov.b64 %0, {%1, %2};" : "=l"(d) : "f"(lo), "f"(hi)); return d;
}
__device__ __forceinline__ float2 unpack2(u64 v) {
    float2 r; asm("mov.b64 {%0, %1}, %2;" : "=f"(r.x), "=f"(r.y) : "l"(v)); return r;
}

// ---------------- scratch ----------------
__device__ unsigned char g_bkt[NBATCH][NH][SL];
__device__ int           g_st[NBATCH][NSL];
__device__ int           g_slotof[NBATCH][NH][SL];
__device__ unsigned      g_locs[NBATCH][SL*NH];
__device__ float         g_slse[NBATCH][NSL];
__device__ float         g_so[(size_t)NBATCH*NSL*D];

// ---------------- K1: LSH buckets; load qk tile once, loop over hashes ----------------
// grid (128, NBATCH), block 256.
__global__ __launch_bounds__(256) void k1_buckets(const float* __restrict__ qk,
                                                  const float* __restrict__ rot) {
    __shared__ float rotT[32*KSTR];   // [n][d]
    __shared__ float qrows[32*KSTR];  // [r][d]
    int stile = blockIdx.x, b = blockIdx.y;
    int tid = threadIdx.x, w = tid >> 5, l = tid & 31;

    const float* qb = qk + ((size_t)b*SL + (size_t)stile*32)*D;
    for (int i = tid; i < 32*D; i += 256) {
        int r = i >> 7, d = i & 127;
        qrows[r*KSTR + d] = qb[r*D + d];
    }

    for (int h = 0; h < NH; h++) {
        __syncthreads();
        for (int i = tid; i < 32*D; i += 256) {
            int n = i & 31, d = i >> 5;
            rotT[n*KSTR + d] = rot[d*(NH*32) + h*32 + n];
        }
        __syncthreads();

        u64 acc2[4] = {0ull,0ull,0ull,0ull};
        for (int d = 0; d < D; d += 4) {
            ulonglong2 rr = *(const ulonglong2*)(rotT + l*KSTR + d);
            #pragma unroll
            for (int r = 0; r < 4; r++) {
                ulonglong2 qq = *(const ulonglong2*)(qrows + (w*4 + r)*KSTR + d);
                acc2[r] = fma2(qq.x, rr.x, acc2[r]);
                acc2[r] = fma2(qq.y, rr.y, acc2[r]);
            }
        }
        #pragma unroll
        for (int r = 0; r < 4; r++) {
            float2 p = unpack2(acc2[r]);
            float a = p.x + p.y;
            float bv = a; int bi = l;
            if (-a > bv) { bv = -a; bi = l + 32; }
            #pragma unroll
            for (int off = 16; off > 0; off >>= 1) {
                float ov = __shfl_xor_sync(0xffffffffu, bv, off);
                int   oi = __shfl_xor_sync(0xffffffffu, bi, off);
                if (ov > bv || (ov == bv && oi < bi)) { bv = ov; bi = oi; }
            }
            if (l == 0) g_bkt[b][h][stile*32 + w*4 + r] = (unsigned char)bi;
        }
    }
}

// ---------------- K2: stable counting sort per (b,h) ----------------
__global__ __launch_bounds__(256) void k2_sort() {
    __shared__ unsigned char  bkt[SL];
    __shared__ unsigned short cnt[NB*257];
    __shared__ int tot[NB];
    __shared__ int base[NB];
    int h = blockIdx.x, b = blockIdx.y;
    int t = threadIdx.x;

    ((int4*)bkt)[t] = ((const int4*)&g_bkt[b][h][0])[t];
    for (int i = t; i < NB*257; i += 256) cnt[i] = 0;
    __syncthreads();

    #pragma unroll
    for (int j = 0; j < 16; j++) {
        int c = bkt[t*16 + j];
        cnt[c*257 + t]++;
    }
    __syncthreads();

    if (t < NB) {
        int run = 0;
        for (int i = 0; i < 256; i++) {
            int v = cnt[t*257 + i];
            cnt[t*257 + i] = (unsigned short)run;
            run += v;
        }
        tot[t] = run;
    }
    __syncthreads();
    if (t == 0) {
        int run = 0;
        for (int c = 0; c < NB; c++) { base[c] = run; run += tot[c]; }
    }
    __syncthreads();

    #pragma unroll
    for (int j = 0; j < 16; j++) {
        int i = t*16 + j;
        int c = bkt[i];
        int r = cnt[c*257 + t]++;
        int slot = h*SL + base[c] + r;
        g_st[b][slot] = i;
        g_slotof[b][h][i] = slot;
        g_locs[b][i*NH + h] = (unsigned)(((h*NB + c) << 9) | (slot >> 6));
    }
}

// ---------------- K3: chunked attention; 16 warps = 8 q-groups x 2 halves ----------------
// grid (NC, NBATCH), block 512, ~176KB smem, 1 CTA/SM.
__global__ __launch_bounds__(512, 1) void k3_attn(const float* __restrict__ qk,
                                                  const float* __restrict__ vglob) {
    extern __shared__ char smraw[];
    u64*   lut = (u64*)smraw;                       // [128][LSTR] lo=lk, hi=lk2
    float* Ksh = (float*)(smraw + 128*LSTR*8);      // [128][KSTR]; reused as reduction scratch
    float* Vsh = Ksh + 128*KSTR;                    // [128][KSTR]
    float* Pt  = Vsh + 128*KSTR;                    // [128][PSTR] transposed probs
    float* nrm = Pt + 128*PSTR;                     // [64]
    int*   stk = (int*)(nrm + 64);                  // [128]
    float* Red = Ksh;                               // [64][KSTR] reduction scratch (aliases Ksh)

    int c = blockIdx.x, b = blockIdx.y;
    int cprev = (c + NC - 1) % NC;
    int tid = threadIdx.x, w = tid >> 5, l = tid & 31;
    int g = w & 7, hv = w >> 3;                     // q-group, half index
    int qbase = g * 8;                              // this q-group owns q rows qbase..qbase+7

    if (tid < 128)
        stk[tid] = g_st[b][(tid < 64 ? c : cprev)*BS + (tid & 63)];
    __syncthreads();

    for (int i = tid; i < 128*NH; i += 512) {
        int z = i >> 3, hh = i & 7;
        unsigned lk = g_locs[b][stk[z]*NH + hh];
        unsigned lk2 = (lk & ~511u) | ((lk + 1u) & 511u);
        lut[z*LSTR + hh] = ((u64)lk2 << 32) | (u64)lk;
    }

    // gather + normalize: warp w handles rows w, w+16, ...
    const float* qkb = qk    + (size_t)b*SL*D;
    const float* vb  = vglob + (size_t)b*SL*D;
    #pragma unroll
    for (int i = 0; i < 8; i++) {
        int r = w + 16*i;
        int tok = stk[r];
        float4 kv = ((const float4*)(qkb + (size_t)tok*D))[l];
        float ss = kv.x*kv.x + kv.y*kv.y + kv.z*kv.z + kv.w*kv.w;
        #pragma unroll
        for (int off = 16; off > 0; off >>= 1) ss += __shfl_xor_sync(0xffffffffu, ss, off);
        float nn = fmaxf(sqrtf(ss), 1e-12f);
        float rn = 1.0f / nn;
        *(float4*)(Ksh + r*KSTR + 4*l) = make_float4(kv.x*rn, kv.y*rn, kv.z*rn, kv.w*rn);
        float4 vv = ((const float4*)(vb + (size_t)tok*D))[l];
        *(float4*)(Vsh + r*KSTR + 4*l) = vv;
        if (r < 64 && l == 0) nrm[r] = nn;
    }
    __syncthreads();

    // ---- QK^T partial: warp (g,hv): 8q x 128z over d in [hv*64, hv*64+64) ----
    u64 a2[8][4];
    #pragma unroll
    for (int qi = 0; qi < 8; qi++)
        #pragma unroll
        for (int j = 0; j < 4; j++) a2[qi][j] = 0ull;

    {
        int d0 = hv * 64;
        for (int s = 0; s < 64; s += 4) {
            int d = d0 + s;
            ulonglong2 kk[4];
            #pragma unroll
            for (int j = 0; j < 4; j++)
                kk[j] = *(const ulonglong2*)(Ksh + (l + 32*j)*KSTR + d);
            #pragma unroll
            for (int qi = 0; qi < 8; qi++) {
                ulonglong2 qq = *(const ulonglong2*)(Ksh + (qbase + qi)*KSTR + d);  // broadcast
                #pragma unroll
                for (int j = 0; j < 4; j++) {
                    a2[qi][j] = fma2(qq.x, kk[j].x, a2[qi][j]);
                    a2[qi][j] = fma2(qq.y, kk[j].y, a2[qi][j]);
                }
            }
        }
    }
    float val[8][4];
    #pragma unroll
    for (int qi = 0; qi < 8; qi++)
        #pragma unroll
        for (int j = 0; j < 4; j++) {
            float2 p = unpack2(a2[qi][j]);
            val[qi][j] = p.x + p.y;
        }
    __syncthreads();   // everyone done reading Ksh

    // hv=1: dump partials into Red (aliases Ksh). hv=0: dup-count meanwhile.
    if (hv == 1) {
        #pragma unroll
        for (int qi = 0; qi < 8; qi++)
            #pragma unroll
            for (int j = 0; j < 4; j++)
                Red[(qbase + qi)*KSTR + l + 32*j] = val[qi][j];
    }

    int cdup[8][4];
    int tk[4]; unsigned bk[4];
    int hq = c >> 6, hkp = cprev >> 6;
    if (hv == 0) {
        #pragma unroll
        for (int j = 0; j < 4; j++) {
            int z = l + 32*j;
            tk[j] = stk[z];
            bk[j] = ((unsigned)lut[z*LSTR + (j < 2 ? hq : hkp)]) >> 9;
        }
        #pragma unroll
        for (int qi = 0; qi < 8; qi++)
            #pragma unroll
            for (int j = 0; j < 4; j++) cdup[qi][j] = 0;
        #pragma unroll
        for (int hh = 0; hh < NH; hh++) {
            unsigned lq[8];
            #pragma unroll
            for (int qi = 0; qi < 8; qi++) lq[qi] = (unsigned)lut[(qbase + qi)*LSTR + hh];
            #pragma unroll
            for (int j = 0; j < 4; j++) {
                u64 pr = lut[(l + 32*j)*LSTR + hh];
                unsigned lk = (unsigned)pr, lk2 = (unsigned)(pr >> 32);
                #pragma unroll
                for (int qi = 0; qi < 8; qi++)
                    cdup[qi][j] += (int)((lq[qi] == lk) | (lq[qi] == lk2));
            }
        }
    }
    __syncthreads();

    // hv=0: combine halves, mask, softmax, write Pt + lse
    if (hv == 0) {
        #pragma unroll
        for (int qi = 0; qi < 8; qi++) {
            int q = qbase + qi;
            int tq = stk[q];
            unsigned bq = ((unsigned)lut[q*LSTR + hq]) >> 9;
            float nq = nrm[q] * SCALE;
            #pragma unroll
            for (int j = 0; j < 4; j++) {
                float v = (val[qi][j] + Red[q*KSTR + l + 32*j]) * nq;
                if (tq <  tk[j]) v = -FLT_MAX;
                if (tq == tk[j]) v = -10000.0f;
                if (bq != bk[j]) v = -FLT_MAX;
                v -= __logf((float)cdup[qi][j] + 1e-9f);
                val[qi][j] = v;
            }
            float m = fmaxf(fmaxf(val[qi][0], val[qi][1]), fmaxf(val[qi][2], val[qi][3]));
            #pragma unroll
            for (int off = 16; off > 0; off >>= 1) m = fmaxf(m, __shfl_xor_sync(0xffffffffu, m, off));
            float s_ = 0.f;
            #pragma unroll
            for (int j = 0; j < 4; j++) s_ += __expf(val[qi][j] - m);
            #pragma unroll
            for (int off = 16; off > 0; off >>= 1) s_ += __shfl_xor_sync(0xffffffffu, s_, off);
            float lse = m + __logf(s_);
            if (l == 0) g_slse[b][c*BS + q] = lse;
            #pragma unroll
            for (int j = 0; j < 4; j++)
                val[qi][j] = __expf(val[qi][j] - lse);
        }
        // Pt[z][q]: two STS.128 per (lane, j) — conflict-free with PSTR=68
        #pragma unroll
        for (int j = 0; j < 4; j++) {
            int z = l + 32*j;
            *(float4*)(Pt + z*PSTR + qbase)     = make_float4(val[0][j], val[1][j], val[2][j], val[3][j]);
            *(float4*)(Pt + z*PSTR + qbase + 4) = make_float4(val[4][j], val[5][j], val[6][j], val[7][j]);
        }
    }
    __syncthreads();

    // ---- P*V partial: warp (g,hv): 8q x cols(4l..4l+3) over z in [hv*64, hv*64+64) ----
    u64 o2[4][4];   // [q-pair][col]
    #pragma unroll
    for (int qp = 0; qp < 4; qp++)
        #pragma unroll
        for (int cc = 0; cc < 4; cc++) o2[qp][cc] = 0ull;

    {
        int z0 = hv * 64;
        for (int s = 0; s < 64; s++) {
            int z = z0 + s;
            float4 vv = *(const float4*)(Vsh + z*KSTR + 4*l);   // conflict-free LDS.128
            u64 v0 = pack2(vv.x, vv.x), v1 = pack2(vv.y, vv.y);
            u64 v2 = pack2(vv.z, vv.z), v3 = pack2(vv.w, vv.w);
            #pragma unroll
            for (int qp = 0; qp < 4; qp++) {
                u64 p2 = *(const u64*)(Pt + z*PSTR + qbase + 2*qp);  // broadcast
                o2[qp][0] = fma2(p2, v0, o2[qp][0]);
                o2[qp][1] = fma2(p2, v1, o2[qp][1]);
                o2[qp][2] = fma2(p2, v2, o2[qp][2]);
                o2[qp][3] = fma2(p2, v3, o2[qp][3]);
            }
        }
    }
    __syncthreads();   // QK-phase Red fully consumed; reuse for PV reduction

    if (hv == 1) {
        #pragma unroll
        for (int qp = 0; qp < 4; qp++) {
            float2 c0 = unpack2(o2[qp][0]);
            float2 c1 = unpack2(o2[qp][1]);
            float2 c2 = unpack2(o2[qp][2]);
            float2 c3 = unpack2(o2[qp][3]);
            int qe = qbase + 2*qp, qo = qe + 1;
            *(float4*)(Red + qe*KSTR + 4*l) = make_float4(c0.x, c1.x, c2.x, c3.x);
            *(float4*)(Red + qo*KSTR + 4*l) = make_float4(c0.y, c1.y, c2.y, c3.y);
        }
    }
    __syncthreads();

    if (hv == 0) {
        float* sob = g_so + ((size_t)b*NSL + (size_t)c*BS)*D;
        #pragma unroll
        for (int qp = 0; qp < 4; qp++) {
            float2 c0 = unpack2(o2[qp][0]);
            float2 c1 = unpack2(o2[qp][1]);
            float2 c2 = unpack2(o2[qp][2]);
            float2 c3 = unpack2(o2[qp][3]);
            int qe = qbase + 2*qp, qo = qe + 1;
            float4 re = *(const float4*)(Red + qe*KSTR + 4*l);
            float4 ro = *(const float4*)(Red + qo*KSTR + 4*l);
            *(float4*)(sob + qe*D + 4*l) = make_float4(c0.x + re.x, c1.x + re.y, c2.x + re.z, c3.x + re.w);
            *(float4*)(sob + qo*D + 4*l) = make_float4(c0.y + ro.x, c1.y + ro.y, c2.y + ro.z, c3.y + ro.w);
        }
    }
}

// ---------------- K4: unsort + cross-hash softmax combine ----------------
__global__ __launch_bounds__(256) void k4_combine(float* __restrict__ out) {
    int tid = threadIdx.x, w = tid >> 5, l = tid & 31;
    int token = blockIdx.x*8 + w;
    int b = token >> 12, s = token & (SL - 1);

    int slotl = 0; float lsel = -FLT_MAX;
    if (l < NH) { slotl = g_slotof[b][l][s]; lsel = g_slse[b][slotl]; }
    int slot[NH]; float lse[NH];
    #pragma unroll
    for (int h = 0; h < NH; h++) {
        slot[h] = __shfl_sync(0xffffffffu, slotl, h);
        lse[h]  = __shfl_sync(0xffffffffu, lsel,  h);
    }
    float m = -FLT_MAX;
    #pragma unroll
    for (int h = 0; h < NH; h++) m = fmaxf(m, lse[h]);
    float Z = 0.f;
    #pragma unroll
    for (int h = 0; h < NH; h++) Z += __expf(lse[h] - m);
    float invZ = 1.f / Z;

    float4 acc = make_float4(0.f, 0.f, 0.f, 0.f);
    #pragma unroll
    for (int h = 0; h < NH; h++) {
        float wgt = __expf(lse[h] - m) * invZ;
        float4 r = *(const float4*)(g_so + ((size_t)b*NSL + (size_t)slot[h])*D + 4*l);
        acc.x += wgt*r.x; acc.y += wgt*r.y; acc.z += wgt*r.z; acc.w += wgt*r.w;
    }
    *((float4*)(out + ((size_t)b*SL + (size_t)s)*D + 4*l)) = acc;
}

// ---------------- launcher ----------------
extern "C" void kernel_launch(void* const* d_in, const int* in_sizes, int n_in,
                              void* d_out, int out_size) {
    const float* qk  = (const float*)d_in[0];
    const float* v   = (const float*)d_in[1];
    const float* rot = (const float*)d_in[2];
    float* out = (float*)d_out;

    const int smem3 = 128*LSTR*8 + (128*KSTR*2 + 128*PSTR + 64)*4 + 128*4;  // 179968 B
    cudaFuncSetAttribute(k3_attn, cudaFuncAttributeMaxDynamicSharedMemorySize, smem3);

    k1_buckets<<<dim3(128, NBATCH), 256>>>(qk, rot);
    k2_sort  <<<dim3(NH, NBATCH), 256>>>();
    k3_attn  <<<dim3(NC, NBATCH), 512, smem3>>>(qk, v);
    k4_combine<<<dim3(4096), 256>>>(out);
}